// round 14
// baseline (speedup 1.0000x reference)
#include <cuda_runtime.h>
#include <math.h>
#include <float.h>

#define H 256
#define G_ 256
#define H2 512
#define E_MAX 524288
#define GT 4                            // graphs per head block
#define NHEADB (G_ / GT)                // 64 head blocks
#define LOGEPS -15.942385152878742f     // logf(FLT_EPSILON)

// ---------------- scratch (static device globals; no allocation) ----------------
__device__ float    d_att[E_MAX];      // att score (candidates); -1e38 for selected
__device__ float    d_sumtok[G_ * H];  // segment sum of edge_tokens
__device__ int      d_cnt[G_];         // edges per graph
__device__ float    d_gsum[G_];        // per-graph Σ exp(att) over candidates
__device__ float    d_u[H];            // att_vec @ W_edge
__device__ float    d_v[H];            // att_vec @ W_query
__device__ float    d_qatt[G_];        // question_tokens @ v
__device__ float    d_WeT[H * H];      // We transposed: WeT[k][j] = We[j][k]
__device__ float    d_W1T[H2 * H];     // W1 transposed: W1T[k][j] = W1[j][k]

// ---------------- K1 (fused): uv (blocks 0..7) + weight transpose (8..199) ------
__global__ void k_pre(const float* __restrict__ We, const float* __restrict__ Wq,
                      const float* __restrict__ W1, const float* __restrict__ av) {
    if (blockIdx.x < 8) {
        // u = att_vec @ W_edge, v = att_vec @ W_query
        __shared__ float sa[H];
        __shared__ float ru[8][32], rv[8][32];
        int tx = threadIdx.x & 31, ty = threadIdx.x >> 5;
        sa[threadIdx.x] = av[threadIdx.x];
        __syncthreads();
        int col = blockIdx.x * 32 + tx;
        float u = 0.0f, v = 0.0f;
        #pragma unroll 4
        for (int j = ty; j < H; j += 8) {
            float a = sa[j];
            u = fmaf(a, We[j * H + col], u);
            v = fmaf(a, Wq[j * H + col], v);
        }
        ru[ty][tx] = u; rv[ty][tx] = v;
        __syncthreads();
        if (ty == 0) {
            float su = 0.0f, sv = 0.0f;
            #pragma unroll
            for (int r = 0; r < 8; r++) { su += ru[r][tx]; sv += rv[r][tx]; }
            d_u[col] = su; d_v[col] = sv;
        }
        return;
    }
    // transpose role: 32x32 tiles
    __shared__ float ts[32][33];
    int id = blockIdx.x - 8;
    int x = threadIdx.x & 31, y = threadIdx.x >> 5;   // y in 0..7
    const float* src; float* dst; int j0, k0, scols;
    if (id < 64) {              // We [256][256] -> d_WeT
        src = We;  dst = d_WeT;
        j0 = (id >> 3) * 32; k0 = (id & 7) * 32; scols = H;
    } else {                    // W1 [256][512] -> d_W1T [512][256]
        id -= 64;
        src = W1;  dst = d_W1T;
        j0 = (id >> 4) * 32; k0 = (id & 15) * 32; scols = H2;
    }
    #pragma unroll
    for (int i = 0; i < 4; i++)
        ts[y + 8 * i][x] = src[(j0 + y + 8 * i) * scols + (k0 + x)];
    __syncthreads();
    #pragma unroll
    for (int i = 0; i < 4; i++)
        dst[(k0 + y + 8 * i) * H + (j0 + x)] = ts[x][y + 8 * i];
}

// ---------------- K1b: qatt[g] = question_tokens[g] . v   + scratch init ----------
__global__ void k_qatt(const float* __restrict__ qt) {
    int g = blockIdx.x, lane = threadIdx.x;
    float4 z = make_float4(0.f, 0.f, 0.f, 0.f);
    ((float4*)d_sumtok)[g * 64 + lane]      = z;
    ((float4*)d_sumtok)[g * 64 + 32 + lane] = z;
    if (lane == 0) { d_cnt[g] = 0; d_gsum[g] = 0.0f; }
    const float4* q4 = (const float4*)(qt + g * H);
    const float4* v4 = (const float4*)d_v;
    float4 a = q4[lane], b = q4[lane + 32];
    float4 va = v4[lane], vb = v4[lane + 32];
    float s = a.x*va.x + a.y*va.y + a.z*va.z + a.w*va.w
            + b.x*vb.x + b.y*vb.y + b.z*vb.z + b.w*vb.w;
    #pragma unroll
    for (int o = 16; o; o >>= 1) s += __shfl_xor_sync(0xffffffffu, s, o);
    if (lane == 0) d_qatt[g] = s;
}

// ---------------- K2: main streaming pass (unroll-2, occ-4, absolute expsum) ----
struct RunState {
    int    cur_g;
    float4 cs0, cs1;
    int    cnt;
    float  rsum;
};

__device__ __forceinline__ void flush_run(const RunState& st, int lane) {
    float* sp = d_sumtok + st.cur_g * H;
    atomicAdd(sp + 4*lane + 0,       st.cs0.x);
    atomicAdd(sp + 4*lane + 1,       st.cs0.y);
    atomicAdd(sp + 4*lane + 2,       st.cs0.z);
    atomicAdd(sp + 4*lane + 3,       st.cs0.w);
    atomicAdd(sp + 128 + 4*lane + 0, st.cs1.x);
    atomicAdd(sp + 128 + 4*lane + 1, st.cs1.y);
    atomicAdd(sp + 128 + 4*lane + 2, st.cs1.z);
    atomicAdd(sp + 128 + 4*lane + 3, st.cs1.w);
    if (lane == 0) {
        atomicAdd(&d_cnt[st.cur_g], st.cnt);
        atomicAdd(&d_gsum[st.cur_g], st.rsum);
    }
}

__device__ __forceinline__ void reset_run(RunState& st, int g) {
    st.cur_g = g;
    st.cs0 = make_float4(0.f, 0.f, 0.f, 0.f);
    st.cs1 = make_float4(0.f, 0.f, 0.f, 0.f);
    st.cnt = 0; st.rsum = 0.0f;
}

__device__ __forceinline__ void proc_edge(RunState& st, float4 a, float4 b,
                                          float s, int g, int m, int e, int lane) {
    if (g != st.cur_g) {
        flush_run(st, lane);
        reset_run(st, g);
    }
    st.cs0.x += a.x; st.cs0.y += a.y; st.cs0.z += a.z; st.cs0.w += a.w;
    st.cs1.x += b.x; st.cs1.y += b.y; st.cs1.z += b.z; st.cs1.w += b.w;
    float t = s + d_qatt[g];
    t = (t > 0.0f) ? t : 0.2f * t;               // LeakyReLU(0.2)
    if (m == 0) {
        t += 0.5f;                               // frontier bonus (candidates)
        st.rsum += __expf(t);                    // absolute-domain exp (range-safe)
    }
    st.cnt++;
    if (lane == 0) d_att[e] = (m == 0) ? t : -1.0e38f;
}

__device__ __forceinline__ float dot8(float4 a, float4 b, float4 ua, float4 ub) {
    float s = a.x*ua.x; s = fmaf(a.y, ua.y, s); s = fmaf(a.z, ua.z, s);
    s = fmaf(a.w, ua.w, s); s = fmaf(b.x, ub.x, s); s = fmaf(b.y, ub.y, s);
    s = fmaf(b.z, ub.z, s); s = fmaf(b.w, ub.w, s);
    return s;
}

__global__ void __launch_bounds__(256, 4)
k_main(const float* __restrict__ et, const int* __restrict__ batch,
       const int* __restrict__ sel, int E, int epw) {
    int wid  = (blockIdx.x * blockDim.x + threadIdx.x) >> 5;
    int lane = threadIdx.x & 31;
    int start = wid * epw;
    if (start >= E) return;
    int end = min(E, start + epw);

    const float4* u4 = (const float4*)d_u;
    float4 ua = u4[lane], ub = u4[lane + 32];

    RunState st;
    reset_run(st, batch[start]);

    int e = start;
    for (; e + 1 < end; e += 2) {
        const float4* r0 = (const float4*)(et + (size_t)e * H);
        const float4* r1 = (const float4*)(et + (size_t)(e + 1) * H);
        float4 a0 = __ldcs(r0 + lane), b0 = __ldcs(r0 + lane + 32);
        float4 a1 = __ldcs(r1 + lane), b1 = __ldcs(r1 + lane + 32);
        int g0 = batch[e], g1 = batch[e + 1];
        int m0 = sel[e],   m1 = sel[e + 1];

        float s0 = dot8(a0, b0, ua, ub);
        float s1 = dot8(a1, b1, ua, ub);
        #pragma unroll
        for (int o = 16; o; o >>= 1) {
            s0 += __shfl_xor_sync(0xffffffffu, s0, o);
            s1 += __shfl_xor_sync(0xffffffffu, s1, o);
        }
        proc_edge(st, a0, b0, s0, g0, m0, e,     lane);
        proc_edge(st, a1, b1, s1, g1, m1, e + 1, lane);
    }
    if (e < end) {   // tail edge
        const float4* r0 = (const float4*)(et + (size_t)e * H);
        float4 a0 = __ldcs(r0 + lane), b0 = __ldcs(r0 + lane + 32);
        int g0 = batch[e], m0 = sel[e];
        float s0 = dot8(a0, b0, ua, ub);
        #pragma unroll
        for (int o = 16; o; o >>= 1) s0 += __shfl_xor_sync(0xffffffffu, s0, o);
        proc_edge(st, a0, b0, s0, g0, m0, e, lane);
    }
    flush_run(st, lane);
}

// ---------------- K3 (fused): head blocks (transposed-weight GEMM) + logits -----
__device__ __forceinline__ void do_head(const float* __restrict__ qt,
                                        const float* __restrict__ lng,
                                        const float* __restrict__ lnb,
                                        const float* __restrict__ b1,
                                        const float* __restrict__ W2,
                                        const float* __restrict__ b2,
                                        float* __restrict__ out_stop,
                                        float* __restrict__ out_pool,
                                        int g0) {
    __shared__ float spool[GT][H];     // 4 KB
    __shared__ float ppool[GT][H];     // 4 KB
    __shared__ float sxn[GT][H2];      // 8 KB
    __shared__ float sh1[GT][H];       // 4 KB
    __shared__ float sred[8][GT];
    __shared__ float smu[GT], sinv[GT];
    int j = threadIdx.x;
    int w = j >> 5, lane = j & 31;
    int gloc = j >> 6;                 // 0..3: graph handled in GEMM phases
    int c4   = j & 63;                 // float4 column group 0..63

    #pragma unroll
    for (int g = 0; g < GT; g++) spool[g][j] = d_sumtok[(g0 + g) * H + j];
    __syncthreads();

    float cinvg = 1.0f / (float)max(d_cnt[g0 + gloc], 1);

    // ---- Phase A: pooled = (We @ spool)/cnt via WeT, coalesced, no shuffles ----
    {
        float4 acc = make_float4(0.f, 0.f, 0.f, 0.f);
        const float4* wt = (const float4*)d_WeT;
        const float* sp = spool[gloc];
        #pragma unroll 8
        for (int k = 0; k < H; k++) {
            float4 wv = wt[k * 64 + c4];
            float s = sp[k];
            acc.x = fmaf(wv.x, s, acc.x); acc.y = fmaf(wv.y, s, acc.y);
            acc.z = fmaf(wv.z, s, acc.z); acc.w = fmaf(wv.w, s, acc.w);
        }
        acc.x *= cinvg; acc.y *= cinvg; acc.z *= cinvg; acc.w *= cinvg;
        ((float4*)ppool[gloc])[c4] = acc;
        ((float4*)(out_pool + (size_t)(g0 + gloc) * H))[c4] = acc;
    }
    __syncthreads();

    // ---- Phase B: LayerNorm over 512 (thread-per-column j) ----
    float pj[GT], x1[GT];
    #pragma unroll
    for (int g = 0; g < GT; g++) {
        pj[g] = ppool[g][j];
        x1[g] = qt[(g0 + g) * H + j];
    }
    #pragma unroll
    for (int g = 0; g < GT; g++) {
        float v = pj[g] + x1[g];
        #pragma unroll
        for (int o = 16; o; o >>= 1) v += __shfl_xor_sync(0xffffffffu, v, o);
        if (lane == 0) sred[w][g] = v;
    }
    __syncthreads();
    if (j < GT) {
        float tot = 0.0f;
        #pragma unroll
        for (int r = 0; r < 8; r++) tot += sred[r][j];
        smu[j] = tot * (1.0f / 512.0f);
    }
    __syncthreads();
    #pragma unroll
    for (int g = 0; g < GT; g++) {
        float d0 = pj[g] - smu[g], d1 = x1[g] - smu[g];
        float v = d0 * d0 + d1 * d1;
        #pragma unroll
        for (int o = 16; o; o >>= 1) v += __shfl_xor_sync(0xffffffffu, v, o);
        if (lane == 0) sred[w][g] = v;
    }
    __syncthreads();
    if (j < GT) {
        float var = 0.0f;
        #pragma unroll
        for (int r = 0; r < 8; r++) var += sred[r][j];
        sinv[j] = rsqrtf(var * (1.0f / 512.0f) + 1e-5f);
    }
    __syncthreads();
    float g0v = lng[j], g1v = lng[H + j], b0v = lnb[j], b1v = lnb[H + j];
    #pragma unroll
    for (int g = 0; g < GT; g++) {
        sxn[g][j]     = (pj[g] - smu[g]) * sinv[g] * g0v + b0v;
        sxn[g][H + j] = (x1[g] - smu[g]) * sinv[g] * g1v + b1v;
    }
    __syncthreads();

    // ---- Phase C: h1pre = W1 @ sxn via W1T, coalesced, no shuffles ----
    {
        float4 acc = make_float4(0.f, 0.f, 0.f, 0.f);
        const float4* wt = (const float4*)d_W1T;
        const float* sx = sxn[gloc];
        #pragma unroll 8
        for (int k = 0; k < H2; k++) {
            float4 wv = wt[k * 64 + c4];
            float s = sx[k];
            acc.x = fmaf(wv.x, s, acc.x); acc.y = fmaf(wv.y, s, acc.y);
            acc.z = fmaf(wv.z, s, acc.z); acc.w = fmaf(wv.w, s, acc.w);
        }
        ((float4*)sh1[gloc])[c4] = acc;
    }
    __syncthreads();

    // ---- Phase D: GELU + W2 reduce (thread-per-column) ----
    float bb = b1[j], w2j = W2[j];
    #pragma unroll
    for (int g = 0; g < GT; g++) {
        float h = sh1[g][j] + bb;
        h = 0.5f * h * (1.0f + erff(h * 0.70710678118654752f));
        float v = h * w2j;
        #pragma unroll
        for (int o = 16; o; o >>= 1) v += __shfl_xor_sync(0xffffffffu, v, o);
        if (lane == 0) sred[w][g] = v;
    }
    __syncthreads();
    if (j < GT) {
        float st = 0.0f;
        #pragma unroll
        for (int r = 0; r < 8; r++) st += sred[r][j];
        out_stop[g0 + j] = st + b2[0];
    }
}

__global__ void __launch_bounds__(256)
k_post(const int* __restrict__ batch,
       const float* __restrict__ qt,
       const float* __restrict__ lng, const float* __restrict__ lnb,
       const float* __restrict__ b1,
       const float* __restrict__ W2, const float* __restrict__ b2,
       float* __restrict__ out_edge, float* __restrict__ out_stop,
       float* __restrict__ out_pool, int E4) {
    if (blockIdx.x < NHEADB) {
        do_head(qt, lng, lnb, b1, W2, b2, out_stop, out_pool, blockIdx.x * GT);
        return;
    }
    // logits role: 2 vec4 items per thread (8 edges)
    int base = (blockIdx.x - NHEADB) * 512 + threadIdx.x;
    #pragma unroll
    for (int rep = 0; rep < 2; rep++) {
        int i = base + rep * 256;
        if (i < E4) {
            int4   g = ((const int4*)batch)[i];
            float4 a = ((const float4*)d_att)[i];
            float4 r;
            r.x = fmaxf(a.x - __logf(fmaxf(d_gsum[g.x], FLT_EPSILON)), LOGEPS);
            r.y = fmaxf(a.y - __logf(fmaxf(d_gsum[g.y], FLT_EPSILON)), LOGEPS);
            r.z = fmaxf(a.z - __logf(fmaxf(d_gsum[g.z], FLT_EPSILON)), LOGEPS);
            r.w = fmaxf(a.w - __logf(fmaxf(d_gsum[g.w], FLT_EPSILON)), LOGEPS);
            ((float4*)out_edge)[i] = r;
        }
    }
}

// tail edges (only if E % 4 != 0)
__global__ void k_logits_tail(const int* __restrict__ batch, float* __restrict__ out,
                              int start, int E) {
    int e = start + blockIdx.x * blockDim.x + threadIdx.x;
    if (e >= E) return;
    out[e] = fmaxf(d_att[e] - __logf(fmaxf(d_gsum[batch[e]], FLT_EPSILON)), LOGEPS);
}

// ---------------- launch ----------------
extern "C" void kernel_launch(void* const* d_in, const int* in_sizes, int n_in,
                              void* d_out, int out_size) {
    const float* edge_tokens     = (const float*)d_in[0];
    const float* question_tokens = (const float*)d_in[1];
    const int*   edge_batch      = (const int*)d_in[2];
    const int*   selected_mask   = (const int*)d_in[3];
    const float* W_edge          = (const float*)d_in[4];
    const float* W_query         = (const float*)d_in[5];
    const float* att_vec         = (const float*)d_in[6];
    const float* ln_g            = (const float*)d_in[7];
    const float* ln_b            = (const float*)d_in[8];
    const float* W1              = (const float*)d_in[9];
    const float* b1              = (const float*)d_in[10];
    const float* W2              = (const float*)d_in[11];
    const float* b2              = (const float*)d_in[12];

    int E = in_sizes[2];
    float* out      = (float*)d_out;
    float* out_edge = out;             // [E]
    float* out_stop = out + E;         // [G]
    float* out_pool = out + E + G_;    // [G, H]

    // uv + weight transpose (8 uv blocks + 64 We tiles + 128 W1 tiles)
    k_pre<<<200, 256>>>(W_edge, W_query, W1, att_vec);
    k_qatt<<<G_, 32>>>(question_tokens);
    // main pass: 4 blocks per SM (148*4 = 592), unroll-2
    {
        int blocks = 592, threads = 256;
        int warps = blocks * threads / 32;        // 4736
        int epw = (E + warps - 1) / warps;
        k_main<<<blocks, threads>>>(edge_tokens, edge_batch, selected_mask, E, epw);
    }
    // fused logits + head
    {
        int E4 = E / 4;
        int nblocks = NHEADB + (E4 + 511) / 512;
        k_post<<<nblocks, 256>>>(edge_batch, question_tokens,
                                 ln_g, ln_b, b1, W2, b2,
                                 out_edge, out_stop, out_pool, E4);
        int rem = E - E4 * 4;
        if (rem > 0)
            k_logits_tail<<<(rem + 255) / 256, 256>>>(edge_batch, out_edge, E4 * 4, E);
    }
}

// round 15
// speedup vs baseline: 1.5679x; 1.5679x over previous
#include <cuda_runtime.h>
#include <math.h>
#include <float.h>

#define H 256
#define G_ 256
#define H2 512
#define E_MAX 524288
#define GT 4                            // graphs per head block
#define NHEADB (G_ / GT)                // 64 head blocks
#define LOGEPS -15.942385152878742f     // logf(FLT_EPSILON)

// ---------------- scratch (static device globals; no allocation) ----------------
__device__ float    d_att[E_MAX];
__device__ float    d_sumtok[G_ * H];
__device__ int      d_cnt[G_];
__device__ float    d_gsum[G_];
__device__ float    d_u[H];
__device__ float    d_v[H];
__device__ float    d_qatt[G_];
__device__ float    d_WeT[H * H];      // WeT[k][j] = We[j][k]
__device__ float    d_W1T[H2 * H];     // W1T[k][j] = W1[j][k]

// ---------------- K1 (fused): uv (blocks 0..7) + weight transpose (8..199) ------
__global__ void k_pre(const float* __restrict__ We, const float* __restrict__ Wq,
                      const float* __restrict__ W1, const float* __restrict__ av) {
    if (blockIdx.x < 8) {
        __shared__ float sa[H];
        __shared__ float ru[8][32], rv[8][32];
        int tx = threadIdx.x & 31, ty = threadIdx.x >> 5;
        sa[threadIdx.x] = av[threadIdx.x];
        __syncthreads();
        int col = blockIdx.x * 32 + tx;
        float u = 0.0f, v = 0.0f;
        #pragma unroll 4
        for (int j = ty; j < H; j += 8) {
            float a = sa[j];
            u = fmaf(a, We[j * H + col], u);
            v = fmaf(a, Wq[j * H + col], v);
        }
        ru[ty][tx] = u; rv[ty][tx] = v;
        __syncthreads();
        if (ty == 0) {
            float su = 0.0f, sv = 0.0f;
            #pragma unroll
            for (int r = 0; r < 8; r++) { su += ru[r][tx]; sv += rv[r][tx]; }
            d_u[col] = su; d_v[col] = sv;
        }
        return;
    }
    // transpose role: 32x32 tiles
    __shared__ float ts[32][33];
    int id = blockIdx.x - 8;
    int x = threadIdx.x & 31, y = threadIdx.x >> 5;
    const float* src; float* dst; int j0, k0, scols;
    if (id < 64) {
        src = We;  dst = d_WeT;
        j0 = (id >> 3) * 32; k0 = (id & 7) * 32; scols = H;
    } else {
        id -= 64;
        src = W1;  dst = d_W1T;
        j0 = (id >> 4) * 32; k0 = (id & 15) * 32; scols = H2;
    }
    #pragma unroll
    for (int i = 0; i < 4; i++)
        ts[y + 8 * i][x] = src[(j0 + y + 8 * i) * scols + (k0 + x)];
    __syncthreads();
    #pragma unroll
    for (int i = 0; i < 4; i++)
        dst[(k0 + y + 8 * i) * H + (j0 + x)] = ts[x][y + 8 * i];
}

// ---------------- K1b: qatt + scratch init ----------
__global__ void k_qatt(const float* __restrict__ qt) {
    int g = blockIdx.x, lane = threadIdx.x;
    float4 z = make_float4(0.f, 0.f, 0.f, 0.f);
    ((float4*)d_sumtok)[g * 64 + lane]      = z;
    ((float4*)d_sumtok)[g * 64 + 32 + lane] = z;
    if (lane == 0) { d_cnt[g] = 0; d_gsum[g] = 0.0f; }
    const float4* q4 = (const float4*)(qt + g * H);
    const float4* v4 = (const float4*)d_v;
    float4 a = q4[lane], b = q4[lane + 32];
    float4 va = v4[lane], vb = v4[lane + 32];
    float s = a.x*va.x + a.y*va.y + a.z*va.z + a.w*va.w
            + b.x*vb.x + b.y*vb.y + b.z*vb.z + b.w*vb.w;
    #pragma unroll
    for (int o = 16; o; o >>= 1) s += __shfl_xor_sync(0xffffffffu, s, o);
    if (lane == 0) d_qatt[g] = s;
}

// ---------------- K2: main streaming pass (unroll-2, occ-4) ----
struct RunState {
    int    cur_g;
    float4 cs0, cs1;
    int    cnt;
    float  rsum;
};

__device__ __forceinline__ void flush_run(const RunState& st, int lane) {
    float* sp = d_sumtok + st.cur_g * H;
    atomicAdd(sp + 4*lane + 0,       st.cs0.x);
    atomicAdd(sp + 4*lane + 1,       st.cs0.y);
    atomicAdd(sp + 4*lane + 2,       st.cs0.z);
    atomicAdd(sp + 4*lane + 3,       st.cs0.w);
    atomicAdd(sp + 128 + 4*lane + 0, st.cs1.x);
    atomicAdd(sp + 128 + 4*lane + 1, st.cs1.y);
    atomicAdd(sp + 128 + 4*lane + 2, st.cs1.z);
    atomicAdd(sp + 128 + 4*lane + 3, st.cs1.w);
    if (lane == 0) {
        atomicAdd(&d_cnt[st.cur_g], st.cnt);
        atomicAdd(&d_gsum[st.cur_g], st.rsum);
    }
}

__device__ __forceinline__ void reset_run(RunState& st, int g) {
    st.cur_g = g;
    st.cs0 = make_float4(0.f, 0.f, 0.f, 0.f);
    st.cs1 = make_float4(0.f, 0.f, 0.f, 0.f);
    st.cnt = 0; st.rsum = 0.0f;
}

__device__ __forceinline__ void proc_edge(RunState& st, float4 a, float4 b,
                                          float s, int g, int m, int e, int lane) {
    if (g != st.cur_g) {
        flush_run(st, lane);
        reset_run(st, g);
    }
    st.cs0.x += a.x; st.cs0.y += a.y; st.cs0.z += a.z; st.cs0.w += a.w;
    st.cs1.x += b.x; st.cs1.y += b.y; st.cs1.z += b.z; st.cs1.w += b.w;
    float t = s + d_qatt[g];
    t = (t > 0.0f) ? t : 0.2f * t;
    if (m == 0) {
        t += 0.5f;
        st.rsum += __expf(t);
    }
    st.cnt++;
    if (lane == 0) d_att[e] = (m == 0) ? t : -1.0e38f;
}

__device__ __forceinline__ float dot8(float4 a, float4 b, float4 ua, float4 ub) {
    float s = a.x*ua.x; s = fmaf(a.y, ua.y, s); s = fmaf(a.z, ua.z, s);
    s = fmaf(a.w, ua.w, s); s = fmaf(b.x, ub.x, s); s = fmaf(b.y, ub.y, s);
    s = fmaf(b.z, ub.z, s); s = fmaf(b.w, ub.w, s);
    return s;
}

__global__ void __launch_bounds__(256, 4)
k_main(const float* __restrict__ et, const int* __restrict__ batch,
       const int* __restrict__ sel, int E, int epw) {
    int wid  = (blockIdx.x * blockDim.x + threadIdx.x) >> 5;
    int lane = threadIdx.x & 31;
    int start = wid * epw;
    if (start >= E) return;
    int end = min(E, start + epw);

    const float4* u4 = (const float4*)d_u;
    float4 ua = u4[lane], ub = u4[lane + 32];

    RunState st;
    reset_run(st, batch[start]);

    int e = start;
    for (; e + 1 < end; e += 2) {
        const float4* r0 = (const float4*)(et + (size_t)e * H);
        const float4* r1 = (const float4*)(et + (size_t)(e + 1) * H);
        float4 a0 = __ldcs(r0 + lane), b0 = __ldcs(r0 + lane + 32);
        float4 a1 = __ldcs(r1 + lane), b1 = __ldcs(r1 + lane + 32);
        int g0 = batch[e], g1 = batch[e + 1];
        int m0 = sel[e],   m1 = sel[e + 1];

        float s0 = dot8(a0, b0, ua, ub);
        float s1 = dot8(a1, b1, ua, ub);
        #pragma unroll
        for (int o = 16; o; o >>= 1) {
            s0 += __shfl_xor_sync(0xffffffffu, s0, o);
            s1 += __shfl_xor_sync(0xffffffffu, s1, o);
        }
        proc_edge(st, a0, b0, s0, g0, m0, e,     lane);
        proc_edge(st, a1, b1, s1, g1, m1, e + 1, lane);
    }
    if (e < end) {
        const float4* r0 = (const float4*)(et + (size_t)e * H);
        float4 a0 = __ldcs(r0 + lane), b0 = __ldcs(r0 + lane + 32);
        int g0 = batch[e], m0 = sel[e];
        float s0 = dot8(a0, b0, ua, ub);
        #pragma unroll
        for (int o = 16; o; o >>= 1) s0 += __shfl_xor_sync(0xffffffffu, s0, o);
        proc_edge(st, a0, b0, s0, g0, m0, e, lane);
    }
    flush_run(st, lane);
}

// ---------------- K3 (fused): smem-tiled split-k head + logits ------------------
// shared layout (floats): [0:4096) tile | [4096:8192) part/sred | [8192:9216) spool/sh1
//                         [9216:10240) ppool | [10240:12288) sxn   == 48 KB
__device__ __forceinline__ void do_head(float* S,
                                        const float* __restrict__ qt,
                                        const float* __restrict__ lng,
                                        const float* __restrict__ lnb,
                                        const float* __restrict__ b1,
                                        const float* __restrict__ W2,
                                        const float* __restrict__ b2,
                                        float* __restrict__ out_stop,
                                        float* __restrict__ out_pool,
                                        int g0) {
    float*  tile  = S;
    float4* tile4 = (float4*)tile;
    float*  part  = S + 4096;
    float4* part4 = (float4*)part;
    float*  spool = S + 8192;       // later reused as sh1
    float*  sh1   = S + 8192;
    float*  ppool = S + 9216;
    float*  sxn   = S + 10240;
    float*  sred  = part;           // 32 floats, time-shared with part
    float*  smu   = part + 40;
    float*  sinv  = part + 44;

    int t = threadIdx.x;
    int ks = t >> 6, c4 = t & 63;   // k-split, column float4-group
    int w = t >> 5, lane = t & 31;

    #pragma unroll
    for (int g = 0; g < GT; g++) spool[g * H + t] = d_sumtok[(g0 + g) * H + t];
    __syncthreads();

    // ---- GEMM1: pooled = S @ WeT  (16 tiles of 16 k-rows) ----
    float4 acc0 = make_float4(0,0,0,0), acc1 = acc0, acc2 = acc0, acc3 = acc0;
    {
        const float4* wt = (const float4*)d_WeT;
        for (int tl = 0; tl < 16; tl++) {
            #pragma unroll
            for (int i = 0; i < 4; i++) {
                int idx = t + 256 * i;
                tile4[idx] = wt[tl * 1024 + idx];
            }
            __syncthreads();
            #pragma unroll
            for (int kk = 0; kk < 4; kk++) {
                int krow = ks * 4 + kk;
                float4 wv = tile4[krow * 64 + c4];
                int kg = tl * 16 + krow;
                float s0 = spool[0 * H + kg], s1 = spool[1 * H + kg];
                float s2 = spool[2 * H + kg], s3 = spool[3 * H + kg];
                acc0.x = fmaf(wv.x, s0, acc0.x); acc0.y = fmaf(wv.y, s0, acc0.y);
                acc0.z = fmaf(wv.z, s0, acc0.z); acc0.w = fmaf(wv.w, s0, acc0.w);
                acc1.x = fmaf(wv.x, s1, acc1.x); acc1.y = fmaf(wv.y, s1, acc1.y);
                acc1.z = fmaf(wv.z, s1, acc1.z); acc1.w = fmaf(wv.w, s1, acc1.w);
                acc2.x = fmaf(wv.x, s2, acc2.x); acc2.y = fmaf(wv.y, s2, acc2.y);
                acc2.z = fmaf(wv.z, s2, acc2.z); acc2.w = fmaf(wv.w, s2, acc2.w);
                acc3.x = fmaf(wv.x, s3, acc3.x); acc3.y = fmaf(wv.y, s3, acc3.y);
                acc3.z = fmaf(wv.z, s3, acc3.z); acc3.w = fmaf(wv.w, s3, acc3.w);
            }
            __syncthreads();
        }
    }
    part4[(ks * 4 + 0) * 64 + c4] = acc0;
    part4[(ks * 4 + 1) * 64 + c4] = acc1;
    part4[(ks * 4 + 2) * 64 + c4] = acc2;
    part4[(ks * 4 + 3) * 64 + c4] = acc3;
    __syncthreads();
    {   // reduce over 4 k-splits; thread = (graph gp, col group cp)
        int gp = t >> 6, cp = t & 63;
        float4 a = part4[(0 + gp) * 64 + cp];
        float4 b = part4[(4 + gp) * 64 + cp];
        float4 c = part4[(8 + gp) * 64 + cp];
        float4 d = part4[(12 + gp) * 64 + cp];
        float cinv = 1.0f / (float)max(d_cnt[g0 + gp], 1);
        float4 r;
        r.x = (a.x + b.x + c.x + d.x) * cinv;
        r.y = (a.y + b.y + c.y + d.y) * cinv;
        r.z = (a.z + b.z + c.z + d.z) * cinv;
        r.w = (a.w + b.w + c.w + d.w) * cinv;
        ((float4*)(ppool + gp * H))[cp] = r;
        ((float4*)(out_pool + (size_t)(g0 + gp) * H))[cp] = r;
    }
    __syncthreads();

    // ---- LayerNorm over 512 (thread-per-column t) ----
    float pj[GT], x1[GT];
    #pragma unroll
    for (int g = 0; g < GT; g++) {
        pj[g] = ppool[g * H + t];
        x1[g] = qt[(g0 + g) * H + t];
    }
    #pragma unroll
    for (int g = 0; g < GT; g++) {
        float v = pj[g] + x1[g];
        #pragma unroll
        for (int o = 16; o; o >>= 1) v += __shfl_xor_sync(0xffffffffu, v, o);
        if (lane == 0) sred[w * 4 + g] = v;
    }
    __syncthreads();
    if (t < GT) {
        float tot = 0.0f;
        #pragma unroll
        for (int r = 0; r < 8; r++) tot += sred[r * 4 + t];
        smu[t] = tot * (1.0f / 512.0f);
    }
    __syncthreads();
    #pragma unroll
    for (int g = 0; g < GT; g++) {
        float d0 = pj[g] - smu[g], d1 = x1[g] - smu[g];
        float v = d0 * d0 + d1 * d1;
        #pragma unroll
        for (int o = 16; o; o >>= 1) v += __shfl_xor_sync(0xffffffffu, v, o);
        if (lane == 0) sred[w * 4 + g] = v;
    }
    __syncthreads();
    if (t < GT) {
        float var = 0.0f;
        #pragma unroll
        for (int r = 0; r < 8; r++) var += sred[r * 4 + t];
        sinv[t] = rsqrtf(var * (1.0f / 512.0f) + 1e-5f);
    }
    __syncthreads();
    {
        float g0v = lng[t], g1v = lng[H + t], b0v = lnb[t], b1v = lnb[H + t];
        #pragma unroll
        for (int g = 0; g < GT; g++) {
            sxn[g * H2 + t]     = (pj[g] - smu[g]) * sinv[g] * g0v + b0v;
            sxn[g * H2 + H + t] = (x1[g] - smu[g]) * sinv[g] * g1v + b1v;
        }
    }
    __syncthreads();

    // ---- GEMM2: h1pre = XN @ W1T  (32 tiles of 16 k-rows over 512) ----
    acc0 = make_float4(0,0,0,0); acc1 = acc0; acc2 = acc0; acc3 = acc0;
    {
        const float4* wt = (const float4*)d_W1T;
        for (int tl = 0; tl < 32; tl++) {
            #pragma unroll
            for (int i = 0; i < 4; i++) {
                int idx = t + 256 * i;
                tile4[idx] = wt[tl * 1024 + idx];
            }
            __syncthreads();
            #pragma unroll
            for (int kk = 0; kk < 4; kk++) {
                int krow = ks * 4 + kk;
                float4 wv = tile4[krow * 64 + c4];
                int kg = tl * 16 + krow;
                float s0 = sxn[0 * H2 + kg], s1 = sxn[1 * H2 + kg];
                float s2 = sxn[2 * H2 + kg], s3 = sxn[3 * H2 + kg];
                acc0.x = fmaf(wv.x, s0, acc0.x); acc0.y = fmaf(wv.y, s0, acc0.y);
                acc0.z = fmaf(wv.z, s0, acc0.z); acc0.w = fmaf(wv.w, s0, acc0.w);
                acc1.x = fmaf(wv.x, s1, acc1.x); acc1.y = fmaf(wv.y, s1, acc1.y);
                acc1.z = fmaf(wv.z, s1, acc1.z); acc1.w = fmaf(wv.w, s1, acc1.w);
                acc2.x = fmaf(wv.x, s2, acc2.x); acc2.y = fmaf(wv.y, s2, acc2.y);
                acc2.z = fmaf(wv.z, s2, acc2.z); acc2.w = fmaf(wv.w, s2, acc2.w);
                acc3.x = fmaf(wv.x, s3, acc3.x); acc3.y = fmaf(wv.y, s3, acc3.y);
                acc3.z = fmaf(wv.z, s3, acc3.z); acc3.w = fmaf(wv.w, s3, acc3.w);
            }
            __syncthreads();
        }
    }
    part4[(ks * 4 + 0) * 64 + c4] = acc0;
    part4[(ks * 4 + 1) * 64 + c4] = acc1;
    part4[(ks * 4 + 2) * 64 + c4] = acc2;
    part4[(ks * 4 + 3) * 64 + c4] = acc3;
    __syncthreads();
    {   // reduce into sh1 (aliases spool; spool no longer needed)
        int gp = t >> 6, cp = t & 63;
        float4 a = part4[(0 + gp) * 64 + cp];
        float4 b = part4[(4 + gp) * 64 + cp];
        float4 c = part4[(8 + gp) * 64 + cp];
        float4 d = part4[(12 + gp) * 64 + cp];
        float4 r;
        r.x = a.x + b.x + c.x + d.x;
        r.y = a.y + b.y + c.y + d.y;
        r.z = a.z + b.z + c.z + d.z;
        r.w = a.w + b.w + c.w + d.w;
        ((float4*)(sh1 + gp * H))[cp] = r;
    }
    __syncthreads();

    // ---- GELU + W2 reduce (thread-per-column) ----
    float bb = b1[t], w2j = W2[t];
    #pragma unroll
    for (int g = 0; g < GT; g++) {
        float h = sh1[g * H + t] + bb;
        h = 0.5f * h * (1.0f + erff(h * 0.70710678118654752f));
        float v = h * w2j;
        #pragma unroll
        for (int o = 16; o; o >>= 1) v += __shfl_xor_sync(0xffffffffu, v, o);
        if (lane == 0) sred[w * 4 + g] = v;
    }
    __syncthreads();
    if (t < GT) {
        float st = 0.0f;
        #pragma unroll
        for (int r = 0; r < 8; r++) st += sred[r * 4 + t];
        out_stop[g0 + t] = st + b2[0];
    }
}

__global__ void __launch_bounds__(256)
k_post(const int* __restrict__ batch,
       const float* __restrict__ qt,
       const float* __restrict__ lng, const float* __restrict__ lnb,
       const float* __restrict__ b1,
       const float* __restrict__ W2, const float* __restrict__ b2,
       float* __restrict__ out_edge, float* __restrict__ out_stop,
       float* __restrict__ out_pool, int E4) {
    __shared__ float S[12288];     // 48 KB
    if (blockIdx.x < NHEADB) {
        do_head(S, qt, lng, lnb, b1, W2, b2, out_stop, out_pool, blockIdx.x * GT);
        return;
    }
    // logits role: 2 vec4 items per thread (8 edges)
    int base = (blockIdx.x - NHEADB) * 512 + threadIdx.x;
    #pragma unroll
    for (int rep = 0; rep < 2; rep++) {
        int i = base + rep * 256;
        if (i < E4) {
            int4   g = ((const int4*)batch)[i];
            float4 a = ((const float4*)d_att)[i];
            float4 r;
            r.x = fmaxf(a.x - __logf(fmaxf(d_gsum[g.x], FLT_EPSILON)), LOGEPS);
            r.y = fmaxf(a.y - __logf(fmaxf(d_gsum[g.y], FLT_EPSILON)), LOGEPS);
            r.z = fmaxf(a.z - __logf(fmaxf(d_gsum[g.z], FLT_EPSILON)), LOGEPS);
            r.w = fmaxf(a.w - __logf(fmaxf(d_gsum[g.w], FLT_EPSILON)), LOGEPS);
            ((float4*)out_edge)[i] = r;
        }
    }
}

__global__ void k_logits_tail(const int* __restrict__ batch, float* __restrict__ out,
                              int start, int E) {
    int e = start + blockIdx.x * blockDim.x + threadIdx.x;
    if (e >= E) return;
    out[e] = fmaxf(d_att[e] - __logf(fmaxf(d_gsum[batch[e]], FLT_EPSILON)), LOGEPS);
}

// ---------------- launch ----------------
extern "C" void kernel_launch(void* const* d_in, const int* in_sizes, int n_in,
                              void* d_out, int out_size) {
    const float* edge_tokens     = (const float*)d_in[0];
    const float* question_tokens = (const float*)d_in[1];
    const int*   edge_batch      = (const int*)d_in[2];
    const int*   selected_mask   = (const int*)d_in[3];
    const float* W_edge          = (const float*)d_in[4];
    const float* W_query         = (const float*)d_in[5];
    const float* att_vec         = (const float*)d_in[6];
    const float* ln_g            = (const float*)d_in[7];
    const float* ln_b            = (const float*)d_in[8];
    const float* W1              = (const float*)d_in[9];
    const float* b1              = (const float*)d_in[10];
    const float* W2              = (const float*)d_in[11];
    const float* b2              = (const float*)d_in[12];

    int E = in_sizes[2];
    float* out      = (float*)d_out;
    float* out_edge = out;             // [E]
    float* out_stop = out + E;         // [G]
    float* out_pool = out + E + G_;    // [G, H]

    k_pre<<<200, 256>>>(W_edge, W_query, W1, att_vec);
    k_qatt<<<G_, 32>>>(question_tokens);
    {
        int blocks = 592, threads = 256;
        int warps = blocks * threads / 32;
        int epw = (E + warps - 1) / warps;
        k_main<<<blocks, threads>>>(edge_tokens, edge_batch, selected_mask, E, epw);
    }
    {
        int E4 = E / 4;
        int nblocks = NHEADB + (E4 + 511) / 512;
        k_post<<<nblocks, 256>>>(edge_batch, question_tokens,
                                 ln_g, ln_b, b1, W2, b2,
                                 out_edge, out_stop, out_pool, E4);
        int rem = E - E4 * 4;
        if (rem > 0)
            k_logits_tail<<<(rem + 255) / 256, 256>>>(edge_batch, out_edge, E4 * 4, E);
    }
}

// round 16
// speedup vs baseline: 1.6550x; 1.0555x over previous
#include <cuda_runtime.h>
#include <math.h>
#include <float.h>

#define H 256
#define G_ 256
#define H2 512
#define E_MAX 524288
#define GT 4                            // graphs per head block
#define NHEADB (G_ / GT)                // 64 head blocks
#define LOGEPS -15.942385152878742f     // logf(FLT_EPSILON)

// ---------------- scratch (static device globals; no allocation) ----------------
__device__ float    d_att[E_MAX];
__device__ float    d_sumtok[G_ * H];
__device__ int      d_cnt[G_];
__device__ float    d_gsum[G_];
__device__ float    d_u[H];
__device__ float    d_v[H];
__device__ float    d_qatt[G_];
__device__ float    d_WeT[H * H];      // WeT[k][j] = We[j][k]
__device__ float    d_W1T[H2 * H];     // W1T[k][j] = W1[j][k]

// ---------------- K1 (fused): uv (blocks 0..7) + weight transpose (8..199) ------
__global__ void k_pre(const float* __restrict__ We, const float* __restrict__ Wq,
                      const float* __restrict__ W1, const float* __restrict__ av) {
    if (blockIdx.x < 8) {
        __shared__ float sa[H];
        __shared__ float ru[8][32], rv[8][32];
        int tx = threadIdx.x & 31, ty = threadIdx.x >> 5;
        sa[threadIdx.x] = av[threadIdx.x];
        __syncthreads();
        int col = blockIdx.x * 32 + tx;
        float u = 0.0f, v = 0.0f;
        #pragma unroll 4
        for (int j = ty; j < H; j += 8) {
            float a = sa[j];
            u = fmaf(a, We[j * H + col], u);
            v = fmaf(a, Wq[j * H + col], v);
        }
        ru[ty][tx] = u; rv[ty][tx] = v;
        __syncthreads();
        if (ty == 0) {
            float su = 0.0f, sv = 0.0f;
            #pragma unroll
            for (int r = 0; r < 8; r++) { su += ru[r][tx]; sv += rv[r][tx]; }
            d_u[col] = su; d_v[col] = sv;
        }
        return;
    }
    // transpose role: 32x32 tiles
    __shared__ float ts[32][33];
    int id = blockIdx.x - 8;
    int x = threadIdx.x & 31, y = threadIdx.x >> 5;
    const float* src; float* dst; int j0, k0, scols;
    if (id < 64) {
        src = We;  dst = d_WeT;
        j0 = (id >> 3) * 32; k0 = (id & 7) * 32; scols = H;
    } else {
        id -= 64;
        src = W1;  dst = d_W1T;
        j0 = (id >> 4) * 32; k0 = (id & 15) * 32; scols = H2;
    }
    #pragma unroll
    for (int i = 0; i < 4; i++)
        ts[y + 8 * i][x] = src[(j0 + y + 8 * i) * scols + (k0 + x)];
    __syncthreads();
    #pragma unroll
    for (int i = 0; i < 4; i++)
        dst[(k0 + y + 8 * i) * H + (j0 + x)] = ts[x][y + 8 * i];
}

// ---------------- K1b: qatt + scratch init ----------
__global__ void k_qatt(const float* __restrict__ qt) {
    int g = blockIdx.x, lane = threadIdx.x;
    float4 z = make_float4(0.f, 0.f, 0.f, 0.f);
    ((float4*)d_sumtok)[g * 64 + lane]      = z;
    ((float4*)d_sumtok)[g * 64 + 32 + lane] = z;
    if (lane == 0) { d_cnt[g] = 0; d_gsum[g] = 0.0f; }
    const float4* q4 = (const float4*)(qt + g * H);
    const float4* v4 = (const float4*)d_v;
    float4 a = q4[lane], b = q4[lane + 32];
    float4 va = v4[lane], vb = v4[lane + 32];
    float s = a.x*va.x + a.y*va.y + a.z*va.z + a.w*va.w
            + b.x*vb.x + b.y*vb.y + b.z*vb.z + b.w*vb.w;
    #pragma unroll
    for (int o = 16; o; o >>= 1) s += __shfl_xor_sync(0xffffffffu, s, o);
    if (lane == 0) d_qatt[g] = s;
}

// ---------------- K2: main streaming pass (unroll-2, occ-4) ----
struct RunState {
    int    cur_g;
    float4 cs0, cs1;
    int    cnt;
    float  rsum;
};

__device__ __forceinline__ void flush_run(const RunState& st, int lane) {
    float* sp = d_sumtok + st.cur_g * H;
    atomicAdd(sp + 4*lane + 0,       st.cs0.x);
    atomicAdd(sp + 4*lane + 1,       st.cs0.y);
    atomicAdd(sp + 4*lane + 2,       st.cs0.z);
    atomicAdd(sp + 4*lane + 3,       st.cs0.w);
    atomicAdd(sp + 128 + 4*lane + 0, st.cs1.x);
    atomicAdd(sp + 128 + 4*lane + 1, st.cs1.y);
    atomicAdd(sp + 128 + 4*lane + 2, st.cs1.z);
    atomicAdd(sp + 128 + 4*lane + 3, st.cs1.w);
    if (lane == 0) {
        atomicAdd(&d_cnt[st.cur_g], st.cnt);
        atomicAdd(&d_gsum[st.cur_g], st.rsum);
    }
}

__device__ __forceinline__ void reset_run(RunState& st, int g) {
    st.cur_g = g;
    st.cs0 = make_float4(0.f, 0.f, 0.f, 0.f);
    st.cs1 = make_float4(0.f, 0.f, 0.f, 0.f);
    st.cnt = 0; st.rsum = 0.0f;
}

__device__ __forceinline__ void proc_edge(RunState& st, float4 a, float4 b,
                                          float s, int g, int m, int e, int lane) {
    if (g != st.cur_g) {
        flush_run(st, lane);
        reset_run(st, g);
    }
    st.cs0.x += a.x; st.cs0.y += a.y; st.cs0.z += a.z; st.cs0.w += a.w;
    st.cs1.x += b.x; st.cs1.y += b.y; st.cs1.z += b.z; st.cs1.w += b.w;
    float t = s + d_qatt[g];
    t = (t > 0.0f) ? t : 0.2f * t;
    if (m == 0) {
        t += 0.5f;
        st.rsum += __expf(t);
    }
    st.cnt++;
    if (lane == 0) d_att[e] = (m == 0) ? t : -1.0e38f;
}

__device__ __forceinline__ float dot8(float4 a, float4 b, float4 ua, float4 ub) {
    float s = a.x*ua.x; s = fmaf(a.y, ua.y, s); s = fmaf(a.z, ua.z, s);
    s = fmaf(a.w, ua.w, s); s = fmaf(b.x, ub.x, s); s = fmaf(b.y, ub.y, s);
    s = fmaf(b.z, ub.z, s); s = fmaf(b.w, ub.w, s);
    return s;
}

__global__ void __launch_bounds__(256, 4)
k_main(const float* __restrict__ et, const int* __restrict__ batch,
       const int* __restrict__ sel, int E, int epw) {
    int wid  = (blockIdx.x * blockDim.x + threadIdx.x) >> 5;
    int lane = threadIdx.x & 31;
    int start = wid * epw;
    if (start >= E) return;
    int end = min(E, start + epw);

    const float4* u4 = (const float4*)d_u;
    float4 ua = u4[lane], ub = u4[lane + 32];

    RunState st;
    reset_run(st, batch[start]);

    int e = start;
    for (; e + 1 < end; e += 2) {
        const float4* r0 = (const float4*)(et + (size_t)e * H);
        const float4* r1 = (const float4*)(et + (size_t)(e + 1) * H);
        float4 a0 = __ldcs(r0 + lane), b0 = __ldcs(r0 + lane + 32);
        float4 a1 = __ldcs(r1 + lane), b1 = __ldcs(r1 + lane + 32);
        int g0 = batch[e], g1 = batch[e + 1];
        int m0 = sel[e],   m1 = sel[e + 1];

        float s0 = dot8(a0, b0, ua, ub);
        float s1 = dot8(a1, b1, ua, ub);
        #pragma unroll
        for (int o = 16; o; o >>= 1) {
            s0 += __shfl_xor_sync(0xffffffffu, s0, o);
            s1 += __shfl_xor_sync(0xffffffffu, s1, o);
        }
        proc_edge(st, a0, b0, s0, g0, m0, e,     lane);
        proc_edge(st, a1, b1, s1, g1, m1, e + 1, lane);
    }
    if (e < end) {
        const float4* r0 = (const float4*)(et + (size_t)e * H);
        float4 a0 = __ldcs(r0 + lane), b0 = __ldcs(r0 + lane + 32);
        int g0 = batch[e], m0 = sel[e];
        float s0 = dot8(a0, b0, ua, ub);
        #pragma unroll
        for (int o = 16; o; o >>= 1) s0 += __shfl_xor_sync(0xffffffffu, s0, o);
        proc_edge(st, a0, b0, s0, g0, m0, e, lane);
    }
    flush_run(st, lane);
}

// ---------------- K3 (fused): double-buffered smem-tiled head + logits ----------
// shared (floats): [0:8192) two 16KB tile buffers (part/sred alias [0:4096))
//                  [8192:9216) spool/sh1 | [9216:10240) ppool | [10240:12288) sxn
__device__ __forceinline__ void gemm_tiled(const float4* __restrict__ wt, int ntiles,
                                           const float* x, int xstride,
                                           float4* tile4, float4* part4,
                                           int t, int ks, int c4) {
    float4 acc0 = make_float4(0,0,0,0), acc1 = acc0, acc2 = acc0, acc3 = acc0;
    float4 p0 = wt[t], p1 = wt[t + 256], p2 = wt[t + 512], p3 = wt[t + 768];
    tile4[t] = p0; tile4[t + 256] = p1; tile4[t + 512] = p2; tile4[t + 768] = p3;
    __syncthreads();
    for (int tl = 0; tl < ntiles; tl++) {
        // prefetch next tile into registers (overlaps compute below)
        if (tl + 1 < ntiles) {
            const float4* src = wt + (tl + 1) * 1024;
            p0 = src[t]; p1 = src[t + 256]; p2 = src[t + 512]; p3 = src[t + 768];
        }
        const float4* tb = tile4 + (tl & 1) * 1024;
        #pragma unroll
        for (int kk = 0; kk < 4; kk++) {
            int krow = ks * 4 + kk;
            float4 wv = tb[krow * 64 + c4];
            int kg = tl * 16 + krow;
            float s0 = x[0 * xstride + kg], s1 = x[1 * xstride + kg];
            float s2 = x[2 * xstride + kg], s3 = x[3 * xstride + kg];
            acc0.x = fmaf(wv.x, s0, acc0.x); acc0.y = fmaf(wv.y, s0, acc0.y);
            acc0.z = fmaf(wv.z, s0, acc0.z); acc0.w = fmaf(wv.w, s0, acc0.w);
            acc1.x = fmaf(wv.x, s1, acc1.x); acc1.y = fmaf(wv.y, s1, acc1.y);
            acc1.z = fmaf(wv.z, s1, acc1.z); acc1.w = fmaf(wv.w, s1, acc1.w);
            acc2.x = fmaf(wv.x, s2, acc2.x); acc2.y = fmaf(wv.y, s2, acc2.y);
            acc2.z = fmaf(wv.z, s2, acc2.z); acc2.w = fmaf(wv.w, s2, acc2.w);
            acc3.x = fmaf(wv.x, s3, acc3.x); acc3.y = fmaf(wv.y, s3, acc3.y);
            acc3.z = fmaf(wv.z, s3, acc3.z); acc3.w = fmaf(wv.w, s3, acc3.w);
        }
        if (tl + 1 < ntiles) {
            float4* nb = tile4 + ((tl + 1) & 1) * 1024;
            nb[t] = p0; nb[t + 256] = p1; nb[t + 512] = p2; nb[t + 768] = p3;
        }
        __syncthreads();    // next buffer ready; current buffer's readers done
    }
    part4[(ks * 4 + 0) * 64 + c4] = acc0;
    part4[(ks * 4 + 1) * 64 + c4] = acc1;
    part4[(ks * 4 + 2) * 64 + c4] = acc2;
    part4[(ks * 4 + 3) * 64 + c4] = acc3;
    __syncthreads();
}

__device__ __forceinline__ void do_head(float* S,
                                        const float* __restrict__ qt,
                                        const float* __restrict__ lng,
                                        const float* __restrict__ lnb,
                                        const float* __restrict__ b1,
                                        const float* __restrict__ W2,
                                        const float* __restrict__ b2,
                                        float* __restrict__ out_stop,
                                        float* __restrict__ out_pool,
                                        int g0) {
    float4* tile4 = (float4*)S;          // 2 x 16KB buffers
    float*  part  = S;                   // aliases tile buf0 (disjoint in time)
    float4* part4 = (float4*)part;
    float*  spool = S + 8192;            // later reused as sh1
    float*  sh1   = S + 8192;
    float*  ppool = S + 9216;
    float*  sxn   = S + 10240;
    float*  sred  = S + 4096;            // in tile buf1 region (disjoint in time)
    float*  smu   = S + 4096 + 40;
    float*  sinv  = S + 4096 + 44;

    int t = threadIdx.x;
    int ks = t >> 6, c4 = t & 63;
    int w = t >> 5, lane = t & 31;

    #pragma unroll
    for (int g = 0; g < GT; g++) spool[g * H + t] = d_sumtok[(g0 + g) * H + t];
    __syncthreads();

    // ---- GEMM1: pooled = S @ WeT (16 tiles), double-buffered ----
    gemm_tiled((const float4*)d_WeT, 16, spool, H, tile4, part4, t, ks, c4);
    {   // reduce over 4 k-splits
        int gp = t >> 6, cp = t & 63;
        float4 a = part4[(0 + gp) * 64 + cp];
        float4 b = part4[(4 + gp) * 64 + cp];
        float4 c = part4[(8 + gp) * 64 + cp];
        float4 d = part4[(12 + gp) * 64 + cp];
        float cinv = 1.0f / (float)max(d_cnt[g0 + gp], 1);
        float4 r;
        r.x = (a.x + b.x + c.x + d.x) * cinv;
        r.y = (a.y + b.y + c.y + d.y) * cinv;
        r.z = (a.z + b.z + c.z + d.z) * cinv;
        r.w = (a.w + b.w + c.w + d.w) * cinv;
        ((float4*)(ppool + gp * H))[cp] = r;
        ((float4*)(out_pool + (size_t)(g0 + gp) * H))[cp] = r;
    }
    __syncthreads();

    // ---- LayerNorm over 512 ----
    float pj[GT], x1[GT];
    #pragma unroll
    for (int g = 0; g < GT; g++) {
        pj[g] = ppool[g * H + t];
        x1[g] = qt[(g0 + g) * H + t];
    }
    #pragma unroll
    for (int g = 0; g < GT; g++) {
        float v = pj[g] + x1[g];
        #pragma unroll
        for (int o = 16; o; o >>= 1) v += __shfl_xor_sync(0xffffffffu, v, o);
        if (lane == 0) sred[w * 4 + g] = v;
    }
    __syncthreads();
    if (t < GT) {
        float tot = 0.0f;
        #pragma unroll
        for (int r = 0; r < 8; r++) tot += sred[r * 4 + t];
        smu[t] = tot * (1.0f / 512.0f);
    }
    __syncthreads();
    #pragma unroll
    for (int g = 0; g < GT; g++) {
        float d0 = pj[g] - smu[g], d1 = x1[g] - smu[g];
        float v = d0 * d0 + d1 * d1;
        #pragma unroll
        for (int o = 16; o; o >>= 1) v += __shfl_xor_sync(0xffffffffu, v, o);
        if (lane == 0) sred[w * 4 + g] = v;
    }
    __syncthreads();
    if (t < GT) {
        float var = 0.0f;
        #pragma unroll
        for (int r = 0; r < 8; r++) var += sred[r * 4 + t];
        sinv[t] = rsqrtf(var * (1.0f / 512.0f) + 1e-5f);
    }
    __syncthreads();
    {
        float g0v = lng[t], g1v = lng[H + t], b0v = lnb[t], b1v = lnb[H + t];
        #pragma unroll
        for (int g = 0; g < GT; g++) {
            sxn[g * H2 + t]     = (pj[g] - smu[g]) * sinv[g] * g0v + b0v;
            sxn[g * H2 + H + t] = (x1[g] - smu[g]) * sinv[g] * g1v + b1v;
        }
    }
    __syncthreads();

    // ---- GEMM2: h1pre = XN @ W1T (32 tiles), double-buffered ----
    gemm_tiled((const float4*)d_W1T, 32, sxn, H2, tile4, part4, t, ks, c4);
    {   // reduce into sh1
        int gp = t >> 6, cp = t & 63;
        float4 a = part4[(0 + gp) * 64 + cp];
        float4 b = part4[(4 + gp) * 64 + cp];
        float4 c = part4[(8 + gp) * 64 + cp];
        float4 d = part4[(12 + gp) * 64 + cp];
        float4 r;
        r.x = a.x + b.x + c.x + d.x;
        r.y = a.y + b.y + c.y + d.y;
        r.z = a.z + b.z + c.z + d.z;
        r.w = a.w + b.w + c.w + d.w;
        ((float4*)(sh1 + gp * H))[cp] = r;
    }
    __syncthreads();

    // ---- GELU + W2 reduce ----
    float bb = b1[t], w2j = W2[t];
    #pragma unroll
    for (int g = 0; g < GT; g++) {
        float h = sh1[g * H + t] + bb;
        h = 0.5f * h * (1.0f + erff(h * 0.70710678118654752f));
        float v = h * w2j;
        #pragma unroll
        for (int o = 16; o; o >>= 1) v += __shfl_xor_sync(0xffffffffu, v, o);
        if (lane == 0) sred[w * 4 + g] = v;
    }
    __syncthreads();
    if (t < GT) {
        float st = 0.0f;
        #pragma unroll
        for (int r = 0; r < 8; r++) st += sred[r * 4 + t];
        out_stop[g0 + t] = st + b2[0];
    }
}

__global__ void __launch_bounds__(256)
k_post(const int* __restrict__ batch,
       const float* __restrict__ qt,
       const float* __restrict__ lng, const float* __restrict__ lnb,
       const float* __restrict__ b1,
       const float* __restrict__ W2, const float* __restrict__ b2,
       float* __restrict__ out_edge, float* __restrict__ out_stop,
       float* __restrict__ out_pool, int E4) {
    __shared__ float S[12288];     // 48 KB
    if (blockIdx.x < NHEADB) {
        do_head(S, qt, lng, lnb, b1, W2, b2, out_stop, out_pool, blockIdx.x * GT);
        return;
    }
    // logits role: 2 vec4 items per thread (8 edges)
    int base = (blockIdx.x - NHEADB) * 512 + threadIdx.x;
    #pragma unroll
    for (int rep = 0; rep < 2; rep++) {
        int i = base + rep * 256;
        if (i < E4) {
            int4   g = ((const int4*)batch)[i];
            float4 a = ((const float4*)d_att)[i];
            float4 r;
            r.x = fmaxf(a.x - __logf(fmaxf(d_gsum[g.x], FLT_EPSILON)), LOGEPS);
            r.y = fmaxf(a.y - __logf(fmaxf(d_gsum[g.y], FLT_EPSILON)), LOGEPS);
            r.z = fmaxf(a.z - __logf(fmaxf(d_gsum[g.z], FLT_EPSILON)), LOGEPS);
            r.w = fmaxf(a.w - __logf(fmaxf(d_gsum[g.w], FLT_EPSILON)), LOGEPS);
            ((float4*)out_edge)[i] = r;
        }
    }
}

__global__ void k_logits_tail(const int* __restrict__ batch, float* __restrict__ out,
                              int start, int E) {
    int e = start + blockIdx.x * blockDim.x + threadIdx.x;
    if (e >= E) return;
    out[e] = fmaxf(d_att[e] - __logf(fmaxf(d_gsum[batch[e]], FLT_EPSILON)), LOGEPS);
}

// ---------------- launch ----------------
extern "C" void kernel_launch(void* const* d_in, const int* in_sizes, int n_in,
                              void* d_out, int out_size) {
    const float* edge_tokens     = (const float*)d_in[0];
    const float* question_tokens = (const float*)d_in[1];
    const int*   edge_batch      = (const int*)d_in[2];
    const int*   selected_mask   = (const int*)d_in[3];
    const float* W_edge          = (const float*)d_in[4];
    const float* W_query         = (const float*)d_in[5];
    const float* att_vec         = (const float*)d_in[6];
    const float* ln_g            = (const float*)d_in[7];
    const float* ln_b            = (const float*)d_in[8];
    const float* W1              = (const float*)d_in[9];
    const float* b1              = (const float*)d_in[10];
    const float* W2              = (const float*)d_in[11];
    const float* b2              = (const float*)d_in[12];

    int E = in_sizes[2];
    float* out      = (float*)d_out;
    float* out_edge = out;             // [E]
    float* out_stop = out + E;         // [G]
    float* out_pool = out + E + G_;    // [G, H]

    k_pre<<<200, 256>>>(W_edge, W_query, W1, att_vec);
    k_qatt<<<G_, 32>>>(question_tokens);
    {
        int blocks = 592, threads = 256;
        int warps = blocks * threads / 32;
        int epw = (E + warps - 1) / warps;
        k_main<<<blocks, threads>>>(edge_tokens, edge_batch, selected_mask, E, epw);
    }
    {
        int E4 = E / 4;
        int nblocks = NHEADB + (E4 + 511) / 512;
        k_post<<<nblocks, 256>>>(edge_batch, question_tokens,
                                 ln_g, ln_b, b1, W2, b2,
                                 out_edge, out_stop, out_pool, E4);
        int rem = E - E4 * 4;
        if (rem > 0)
            k_logits_tail<<<(rem + 255) / 256, 256>>>(edge_batch, out_edge, E4 * 4, E);
    }
}